// round 13
// baseline (speedup 1.0000x reference)
#include <cuda_runtime.h>
#include <cuda_fp16.h>
#include <math.h>
#include <stdint.h>

#define MAXN 100000
#define MAXE 1600000
#define IN_SIZE 256
#define OUT_SIZE 64

// ---------------- device scratch (no allocation allowed) ----------------
__device__ __align__(256) __half    g_xwh[MAXN * OUT_SIZE];     // dinv-scaled X@W^T fp16
__device__ __align__(256) uint32_t  g_wt[IN_SIZE * OUT_SIZE];   // W^T tf32, [k][n]
__device__ __align__(256) float     g_dinv[MAXN];               // D^{-1/2}
__device__ __align__(256) int       g_deg[MAXN];                // non-self degree
__device__ __align__(256) int       g_rowstart[MAXN];           // global CSR offsets
__device__ __align__(256) int       g_slot[MAXE];               // per-edge slot in row
__device__ __align__(256) int       g_col[MAXE];                // CSR column indices
__device__ int      g_total;      // reset by k_agg each run
__device__ unsigned g_barctr;     // CSR-group barrier counter
__device__ unsigned g_gctr;       // grid-wide barrier counter
__device__ unsigned g_wt_ready;   // W-tf32 ready flag (set by GEMM block 0)

__device__ __forceinline__ uint32_t f2tf(float f) {
    uint32_t r;
    asm("cvt.rna.tf32.f32 %0, %1;" : "=r"(r) : "f"(f));
    return r;
}

__device__ __forceinline__ void cp16(void* smem, const void* g, int valid) {
    uint32_t s = (uint32_t)__cvta_generic_to_shared(smem);
    asm volatile("cp.async.cg.shared.global [%0], [%1], 16, %2;"
                 :: "r"(s), "l"(g), "r"(valid ? 16 : 0));
}
__device__ __forceinline__ void cp_commit() { asm volatile("cp.async.commit_group;"); }
template <int n> __device__ __forceinline__ void cp_wait() {
    asm volatile("cp.async.wait_group %0;" :: "n"(n));
}

__device__ __forceinline__ unsigned ld_acq(const unsigned* p) {
    unsigned v;
    asm volatile("ld.acquire.gpu.u32 %0, [%1];" : "=r"(v) : "l"(p) : "memory");
    return v;
}
__device__ __forceinline__ void st_rel(unsigned* p, unsigned v) {
    asm volatile("st.release.gpu.u32 [%0], %1;" :: "l"(p), "r"(v) : "memory");
}

// CSR-group barrier
__device__ __forceinline__ void csr_barrier(unsigned target) {
    __syncthreads();
    if (threadIdx.x == 0) {
        __threadfence();
        atomicAdd(&g_barctr, 1u);
        while (ld_acq(&g_barctr) < target) __nanosleep(64);
    }
    __syncthreads();
}

// ---------------- mega: GEMM blocks || CSR blocks, barrier, scale ----------------
#define GM 128
#define GK 32
#define AS 36
#define WS 72
#define A_BUF (GM * AS)
#define W_BUF (GK * WS)
#define GEMM_SMEM ((2 * A_BUF + 2 * W_BUF) * 4)   // 55296 B

__global__ __launch_bounds__(256) void k_mega(const int* __restrict__ ei,
                                              const float* __restrict__ x,
                                              const float* __restrict__ W,
                                              int N, int E, int tiles,
                                              int gemmBlocks, int nCsr, int nBlocks) {
    extern __shared__ float dyn[];
    int tid = threadIdx.x;

    if ((int)blockIdx.x < gemmBlocks) {
        // ================= GEMM role =================
        // Block 0 converts W -> g_wt (tf32) once; others spin on the flag.
        if (blockIdx.x == 0) {
            for (int i = tid; i < IN_SIZE * OUT_SIZE; i += 256) {
                int k = i >> 6;
                int n = i & 63;
                g_wt[i] = f2tf(W[n * IN_SIZE + k]);
            }
            __syncthreads();
            if (tid == 0) { __threadfence(); st_rel(&g_wt_ready, 1u); }
        } else {
            if (tid == 0) {
                while (ld_acq(&g_wt_ready) == 0u) __nanosleep(64);
            }
            __syncthreads();
        }

        float*    sA[2] = {dyn, dyn + A_BUF};
        uint32_t* sWb   = reinterpret_cast<uint32_t*>(dyn + 2 * A_BUF);
        uint32_t* sW[2] = {sWb, sWb + W_BUF};

        int warp = tid >> 5;
        int lane = tid & 31;
        int gid  = lane >> 2;
        int tig  = lane & 3;
        int mw   = warp * 16;

        auto loadA = [&](int m0, int k0, float* buf) {
#pragma unroll
            for (int it = 0; it < 4; it++) {
                int idx = tid + it * 256;
                int m   = idx >> 3;
                int kq  = idx & 7;
                int gm  = m0 + m;
                int ok  = gm < N;
                int row = ok ? gm : 0;
                cp16(&buf[m * AS + kq * 4], &x[(size_t)row * IN_SIZE + k0 + kq * 4], ok);
            }
        };
        auto loadW = [&](int k0, uint32_t* buf) {
#pragma unroll
            for (int it = 0; it < 2; it++) {
                int idx = tid + it * 256;      // 0..511
                int k   = idx >> 4;            // 0..31
                int nq  = idx & 15;            // 0..15
                cp16(&buf[k * WS + nq * 4], &g_wt[(k0 + k) * OUT_SIZE + nq * 4], 1);
            }
        };

        for (int t = blockIdx.x; t < tiles; t += gemmBlocks) {
            int m0 = t * GM;

            float acc[8][4];
#pragma unroll
            for (int j = 0; j < 8; j++)
#pragma unroll
                for (int q = 0; q < 4; q++) acc[j][q] = 0.0f;

            loadA(m0, 0, sA[0]);
            loadW(0, sW[0]);
            cp_commit();

#pragma unroll 1
            for (int i = 0; i < IN_SIZE / GK; i++) {
                if (i < IN_SIZE / GK - 1) {
                    loadA(m0, (i + 1) * GK, sA[(i + 1) & 1]);
                    loadW((i + 1) * GK, sW[(i + 1) & 1]);
                    cp_commit();
                    cp_wait<1>();
                } else {
                    cp_wait<0>();
                }
                __syncthreads();

                const float*    a_s = sA[i & 1];
                const uint32_t* w_s = sW[i & 1];
#pragma unroll
                for (int ks = 0; ks < 4; ks++) {
                    int kk = ks * 8;
                    uint32_t a0 = f2tf(a_s[(mw + gid)     * AS + kk + tig]);
                    uint32_t a1 = f2tf(a_s[(mw + gid + 8) * AS + kk + tig]);
                    uint32_t a2 = f2tf(a_s[(mw + gid)     * AS + kk + tig + 4]);
                    uint32_t a3 = f2tf(a_s[(mw + gid + 8) * AS + kk + tig + 4]);
#pragma unroll
                    for (int j = 0; j < 8; j++) {
                        uint32_t b0 = w_s[(kk + tig)     * WS + j * 8 + gid];
                        uint32_t b1 = w_s[(kk + tig + 4) * WS + j * 8 + gid];
                        asm volatile(
                            "mma.sync.aligned.m16n8k8.row.col.f32.tf32.tf32.f32 "
                            "{%0,%1,%2,%3}, {%4,%5,%6,%7}, {%8,%9}, {%0,%1,%2,%3};"
                            : "+f"(acc[j][0]), "+f"(acc[j][1]), "+f"(acc[j][2]), "+f"(acc[j][3])
                            : "r"(a0), "r"(a1), "r"(a2), "r"(a3), "r"(b0), "r"(b1));
                    }
                }
                __syncthreads();
            }

            int r0 = m0 + mw + gid;
#pragma unroll
            for (int j = 0; j < 8; j++) {
                if (r0 < N) {
                    __half2 h = __floats2half2_rn(acc[j][0], acc[j][1]);
                    *reinterpret_cast<__half2*>(&g_xwh[(size_t)r0 * OUT_SIZE + j * 8 + 2 * tig]) = h;
                }
                if (r0 + 8 < N) {
                    __half2 h = __floats2half2_rn(acc[j][2], acc[j][3]);
                    *reinterpret_cast<__half2*>(&g_xwh[(size_t)(r0 + 8) * OUT_SIZE + j * 8 + 2 * tig]) = h;
                }
            }
            __syncthreads();
        }
    } else {
        // ================= CSR role =================
        int csrRank = blockIdx.x - gemmBlocks;
        int Tcsr    = nCsr * 256;
        int gtid    = csrRank * 256 + tid;

        // phase 0: zero degrees
        for (int i = gtid; i < N; i += Tcsr) g_deg[i] = 0;
        csr_barrier((unsigned)nCsr);

        // phase 1: count non-self edges, record slot (4-edge batches)
        {
            int e = gtid;
            for (; e + 3 * Tcsr < E; e += 4 * Tcsr) {
                int e0 = e, e1 = e + Tcsr, e2 = e + 2 * Tcsr, e3 = e + 3 * Tcsr;
                int r0 = ei[e0], r1 = ei[e1], r2 = ei[e2], r3 = ei[e3];
                int c0 = ei[E + e0], c1 = ei[E + e1], c2 = ei[E + e2], c3 = ei[E + e3];
                if (r0 != c0) g_slot[e0] = atomicAdd(&g_deg[r0], 1);
                if (r1 != c1) g_slot[e1] = atomicAdd(&g_deg[r1], 1);
                if (r2 != c2) g_slot[e2] = atomicAdd(&g_deg[r2], 1);
                if (r3 != c3) g_slot[e3] = atomicAdd(&g_deg[r3], 1);
            }
            for (; e < E; e += Tcsr) {
                int r = ei[e], c = ei[E + e];
                if (r != c) g_slot[e] = atomicAdd(&g_deg[r], 1);
            }
        }
        csr_barrier((unsigned)(2 * nCsr));

        // phase 2: chunked exclusive scan -> rowstart; dinv fused
        {
            int* swsum = reinterpret_cast<int*>(dyn);   // 8 ints
            __shared__ int schunkbase;
            int lane = tid & 31;
            int w    = tid >> 5;
            int nChunks = (N + 255) >> 8;
            for (int chunk = csrRank; chunk < nChunks; chunk += nCsr) {
                int i = chunk * 256 + tid;
                int v = (i < N) ? __ldcg(&g_deg[i]) : 0;
                if (i < N) g_dinv[i] = rsqrtf((float)(v + 1));   // +1: self loop
                int p = v;
#pragma unroll
                for (int off = 1; off < 32; off <<= 1) {
                    int tt = __shfl_up_sync(0xffffffffu, p, off);
                    if (lane >= off) p += tt;
                }
                if (lane == 31) swsum[w] = p;
                __syncthreads();
                if (tid == 0) {
                    int run = 0;
#pragma unroll
                    for (int k = 0; k < 8; k++) { int s = swsum[k]; swsum[k] = run; run += s; }
                    schunkbase = atomicAdd(&g_total, run);
                }
                __syncthreads();
                if (i < N) g_rowstart[i] = schunkbase + swsum[w] + p - v;
                __syncthreads();
            }
        }
        csr_barrier((unsigned)(3 * nCsr));

        // phase 3: scatter columns (4-edge batches)
        {
            int e = gtid;
            for (; e + 3 * Tcsr < E; e += 4 * Tcsr) {
                int e0 = e, e1 = e + Tcsr, e2 = e + 2 * Tcsr, e3 = e + 3 * Tcsr;
                int r0 = ei[e0], r1 = ei[e1], r2 = ei[e2], r3 = ei[e3];
                int c0 = ei[E + e0], c1 = ei[E + e1], c2 = ei[E + e2], c3 = ei[E + e3];
                int rs0 = __ldcg(&g_rowstart[r0]);
                int rs1 = __ldcg(&g_rowstart[r1]);
                int rs2 = __ldcg(&g_rowstart[r2]);
                int rs3 = __ldcg(&g_rowstart[r3]);
                int sl0 = __ldcg(&g_slot[e0]);
                int sl1 = __ldcg(&g_slot[e1]);
                int sl2 = __ldcg(&g_slot[e2]);
                int sl3 = __ldcg(&g_slot[e3]);
                if (r0 != c0) g_col[rs0 + sl0] = c0;
                if (r1 != c1) g_col[rs1 + sl1] = c1;
                if (r2 != c2) g_col[rs2 + sl2] = c2;
                if (r3 != c3) g_col[rs3 + sl3] = c3;
            }
            for (; e < E; e += Tcsr) {
                int r = ei[e], c = ei[E + e];
                if (r != c) g_col[__ldcg(&g_rowstart[r]) + __ldcg(&g_slot[e])] = c;
            }
        }
    }

    // ---------- grid-wide barrier (one-wave grid) ----------
    __syncthreads();
    if (tid == 0) {
        __threadfence();
        atomicAdd(&g_gctr, 1u);
        while (ld_acq(&g_gctr) < (unsigned)nBlocks) __nanosleep(64);
    }
    __syncthreads();

    // ---------- scale phase: xwh[i,:] *= dinv[i] ----------
    {
        uint4* xh4 = reinterpret_cast<uint4*>(g_xwh);
        int gidx  = blockIdx.x * 256 + tid;
        int total = N * 8;
        int step  = nBlocks * 256;
        for (int idx = gidx; idx < total; idx += step) {
            int row = idx >> 3;
            float d = __ldcg(&g_dinv[row]);
            uint4 v = __ldcg(&xh4[idx]);
            __half2* h = reinterpret_cast<__half2*>(&v);
#pragma unroll
            for (int q = 0; q < 4; q++) {
                float2 f = __half22float2(h[q]);
                h[q] = __floats2half2_rn(d * f.x, d * f.y);
            }
            xh4[idx] = v;
        }
    }
}

// ---------------- aggregation: out[r] = dinv[r]*(xwh[r] + sum_c xwh[c]) ----------------
__device__ __forceinline__ void h8_add(uint4 v, float* acc) {
    const __half2* h = reinterpret_cast<const __half2*>(&v);
#pragma unroll
    for (int q = 0; q < 4; q++) {
        float2 f = __half22float2(h[q]);
        acc[2 * q]     += f.x;
        acc[2 * q + 1] += f.y;
    }
}

__device__ __forceinline__ uint4 h8_pair(uint4 a, uint4 b) {
    const __half2* ha = reinterpret_cast<const __half2*>(&a);
    const __half2* hb = reinterpret_cast<const __half2*>(&b);
    uint4 r;
    __half2* hr = reinterpret_cast<__half2*>(&r);
#pragma unroll
    for (int q = 0; q < 4; q++) hr[q] = __hadd2(ha[q], hb[q]);
    return r;
}

__global__ __launch_bounds__(256) void k_agg(float* __restrict__ out, int N) {
    // reset mega's counters for the next replay (no agg block reads them)
    if (blockIdx.x == 0 && threadIdx.x == 0) {
        g_barctr = 0u; g_gctr = 0u; g_total = 0; g_wt_ready = 0u;
    }

    int t   = blockIdx.x * blockDim.x + threadIdx.x;
    int row = t >> 3;          // 8 lanes per row
    int l   = t & 7;
    if (row >= N) return;

    const uint4* xh = reinterpret_cast<const uint4*>(g_xwh);
    float dr = g_dinv[row];

    float acc[8];
#pragma unroll
    for (int q = 0; q < 8; q++) acc[q] = 0.0f;
    h8_add(xh[(size_t)row * 8 + l], acc);   // self loop (already dinv-scaled)

    int s0  = g_rowstart[row];
    int cnt = g_deg[row];

    int j = 0;
    for (; j + 4 <= cnt; j += 4) {
        int c0 = __ldg(&g_col[s0 + j]);
        int c1 = __ldg(&g_col[s0 + j + 1]);
        int c2 = __ldg(&g_col[s0 + j + 2]);
        int c3 = __ldg(&g_col[s0 + j + 3]);
        uint4 v0 = xh[(size_t)c0 * 8 + l];
        uint4 v1 = xh[(size_t)c1 * 8 + l];
        uint4 v2 = xh[(size_t)c2 * 8 + l];
        uint4 v3 = xh[(size_t)c3 * 8 + l];
        // 4-term fp16 tree, single convert to fp32
        h8_add(h8_pair(h8_pair(v0, v1), h8_pair(v2, v3)), acc);
    }
    for (; j < cnt; j++) {
        int c = __ldg(&g_col[s0 + j]);
        h8_add(xh[(size_t)c * 8 + l], acc);
    }

    float4 o0 = make_float4(dr * acc[0], dr * acc[1], dr * acc[2], dr * acc[3]);
    float4 o1 = make_float4(dr * acc[4], dr * acc[5], dr * acc[6], dr * acc[7]);
    float4* dst = reinterpret_cast<float4*>(out + (size_t)row * OUT_SIZE + l * 8);
    dst[0] = o0;
    dst[1] = o1;
}

// ---------------------------------------------------------------------------
extern "C" void kernel_launch(void* const* d_in, const int* in_sizes, int n_in,
                              void* d_out, int out_size) {
    const int*   ei = (const int*)d_in[0];     // [2, E]
    const float* x  = (const float*)d_in[1];   // [N, 256]
    const float* W  = (const float*)d_in[3];   // [64, 256]
    float* out = (float*)d_out;

    int E = in_sizes[0] / 2;
    int N = in_sizes[1] / IN_SIZE;

    cudaFuncSetAttribute(k_mega, cudaFuncAttributeMaxDynamicSharedMemorySize, GEMM_SMEM);

    int dev = 0;
    cudaGetDevice(&dev);
    int sms = 0;
    cudaDeviceGetAttribute(&sms, cudaDevAttrMultiProcessorCount, dev);
    int mb = 0;
    cudaOccupancyMaxActiveBlocksPerMultiprocessor(&mb, k_mega, 256, GEMM_SMEM);
    if (mb < 1) mb = 1;
    if (sms < 1) sms = 148;

    int nBlocks = sms * mb;                       // exactly one resident wave
    int tiles   = (N + GM - 1) / GM;
    int gemmB   = (nBlocks * 7) / 16;             // ~0.44 GEMM / 0.56 CSR (R11 optimum)
    if (gemmB < 1) gemmB = 1;
    if (gemmB > nBlocks - 1) gemmB = nBlocks - 1;
    int nCsr = nBlocks - gemmB;

    k_mega<<<nBlocks, 256, GEMM_SMEM>>>(ei, x, W, N, E, tiles, gemmB, nCsr, nBlocks);
    k_agg <<<(N * 8 + 255) / 256, 256>>>(out, N);
}

// round 14
// speedup vs baseline: 1.0486x; 1.0486x over previous
#include <cuda_runtime.h>
#include <cuda_fp16.h>
#include <math.h>
#include <stdint.h>

#define MAXN 100000
#define MAXE 1600000
#define IN_SIZE 256
#define OUT_SIZE 64

// ---------------- device scratch (no allocation allowed) ----------------
__device__ __align__(256) __half    g_xwh[MAXN * OUT_SIZE];     // dinv-scaled X@W^T fp16
__device__ __align__(256) uint32_t  g_wt[IN_SIZE * OUT_SIZE];   // W^T tf32, [k][n]
__device__ __align__(256) float     g_dinv[MAXN];               // D^{-1/2}
__device__ __align__(256) int       g_deg[MAXN];                // non-self degree
__device__ __align__(256) int       g_rowstart[MAXN];           // global CSR offsets
__device__ __align__(256) int       g_slot[MAXE];               // per-edge slot in row
__device__ __align__(256) int       g_col[MAXE];                // CSR column indices
__device__ int      g_total;      // scan base; reset by k_agg
__device__ unsigned g_gctr;       // grid barrier counter; reset by k_agg

__device__ __forceinline__ uint32_t f2tf(float f) {
    uint32_t r;
    asm("cvt.rna.tf32.f32 %0, %1;" : "=r"(r) : "f"(f));
    return r;
}

__device__ __forceinline__ void cp16(void* smem, const void* g, int valid) {
    uint32_t s = (uint32_t)__cvta_generic_to_shared(smem);
    asm volatile("cp.async.cg.shared.global [%0], [%1], 16, %2;"
                 :: "r"(s), "l"(g), "r"(valid ? 16 : 0));
}
__device__ __forceinline__ void cp_commit() { asm volatile("cp.async.commit_group;"); }
template <int n> __device__ __forceinline__ void cp_wait() {
    asm volatile("cp.async.wait_group %0;" :: "n"(n));
}

__device__ __forceinline__ unsigned ld_acq(const unsigned* p) {
    unsigned v;
    asm volatile("ld.acquire.gpu.u32 %0, [%1];" : "=r"(v) : "l"(p) : "memory");
    return v;
}

// full-grid barrier (one-wave grid), monotonic counter
__device__ __forceinline__ void grid_barrier(int phase, int nBlocks) {
    __syncthreads();
    if (threadIdx.x == 0) {
        __threadfence();
        atomicAdd(&g_gctr, 1u);
        unsigned target = (unsigned)(phase * nBlocks);
        while (ld_acq(&g_gctr) < target) __nanosleep(64);
    }
    __syncthreads();
}

// ---------------- mega: serial full-chip phases in one persistent kernel ----------------
#define GM 128
#define GK 32
#define AS 36
#define WS 72
#define A_BUF (GM * AS)
#define W_BUF (GK * WS)
#define GEMM_SMEM ((2 * A_BUF + 2 * W_BUF) * 4)   // 55296 B

__global__ __launch_bounds__(256) void k_mega(const int* __restrict__ ei,
                                              const float* __restrict__ x,
                                              const float* __restrict__ W,
                                              int N, int E, int tiles, int nBlocks) {
    extern __shared__ float dyn[];
    int tid  = threadIdx.x;
    int gtid = blockIdx.x * 256 + tid;
    int T    = nBlocks * 256;

    // ---- phase 0: zero degrees + W^T tf32 convert ----
    for (int i = gtid; i < N; i += T) g_deg[i] = 0;
    for (int i = gtid; i < IN_SIZE * OUT_SIZE; i += T) {
        int k = i >> 6;
        int n = i & 63;
        g_wt[i] = f2tf(W[n * IN_SIZE + k]);
    }
    grid_barrier(1, nBlocks);

    // ---- phase 1: count non-self edges, record slot (4-edge batches) ----
    {
        int e = gtid;
        for (; e + 3 * T < E; e += 4 * T) {
            int e0 = e, e1 = e + T, e2 = e + 2 * T, e3 = e + 3 * T;
            int r0 = ei[e0], r1 = ei[e1], r2 = ei[e2], r3 = ei[e3];
            int c0 = ei[E + e0], c1 = ei[E + e1], c2 = ei[E + e2], c3 = ei[E + e3];
            if (r0 != c0) g_slot[e0] = atomicAdd(&g_deg[r0], 1);
            if (r1 != c1) g_slot[e1] = atomicAdd(&g_deg[r1], 1);
            if (r2 != c2) g_slot[e2] = atomicAdd(&g_deg[r2], 1);
            if (r3 != c3) g_slot[e3] = atomicAdd(&g_deg[r3], 1);
        }
        for (; e < E; e += T) {
            int r = ei[e], c = ei[E + e];
            if (r != c) g_slot[e] = atomicAdd(&g_deg[r], 1);
        }
    }
    grid_barrier(2, nBlocks);

    // ---- phase 2: chunked exclusive scan -> rowstart; dinv fused ----
    {
        int* swsum = reinterpret_cast<int*>(dyn);   // 8 ints
        __shared__ int schunkbase;
        int lane = tid & 31;
        int w    = tid >> 5;
        int nChunks = (N + 255) >> 8;
        for (int chunk = blockIdx.x; chunk < nChunks; chunk += nBlocks) {
            int i = chunk * 256 + tid;
            int v = (i < N) ? __ldcg(&g_deg[i]) : 0;
            if (i < N) g_dinv[i] = rsqrtf((float)(v + 1));   // +1: self loop
            int p = v;
#pragma unroll
            for (int off = 1; off < 32; off <<= 1) {
                int tt = __shfl_up_sync(0xffffffffu, p, off);
                if (lane >= off) p += tt;
            }
            if (lane == 31) swsum[w] = p;
            __syncthreads();
            if (tid == 0) {
                int run = 0;
#pragma unroll
                for (int k = 0; k < 8; k++) { int s = swsum[k]; swsum[k] = run; run += s; }
                schunkbase = atomicAdd(&g_total, run);
            }
            __syncthreads();
            if (i < N) g_rowstart[i] = schunkbase + swsum[w] + p - v;
            __syncthreads();
        }
    }
    grid_barrier(3, nBlocks);

    // ---- phase 3: scatter columns (4-edge batches) ----
    // (no barrier after: GEMM below touches disjoint state, blocks flow through)
    {
        int e = gtid;
        for (; e + 3 * T < E; e += 4 * T) {
            int e0 = e, e1 = e + T, e2 = e + 2 * T, e3 = e + 3 * T;
            int r0 = ei[e0], r1 = ei[e1], r2 = ei[e2], r3 = ei[e3];
            int c0 = ei[E + e0], c1 = ei[E + e1], c2 = ei[E + e2], c3 = ei[E + e3];
            int rs0 = __ldcg(&g_rowstart[r0]);
            int rs1 = __ldcg(&g_rowstart[r1]);
            int rs2 = __ldcg(&g_rowstart[r2]);
            int rs3 = __ldcg(&g_rowstart[r3]);
            int sl0 = __ldcg(&g_slot[e0]);
            int sl1 = __ldcg(&g_slot[e1]);
            int sl2 = __ldcg(&g_slot[e2]);
            int sl3 = __ldcg(&g_slot[e3]);
            if (r0 != c0) g_col[rs0 + sl0] = c0;
            if (r1 != c1) g_col[rs1 + sl1] = c1;
            if (r2 != c2) g_col[rs2 + sl2] = c2;
            if (r3 != c3) g_col[rs3 + sl3] = c3;
        }
        for (; e < E; e += T) {
            int r = ei[e], c = ei[E + e];
            if (r != c) g_col[__ldcg(&g_rowstart[r]) + __ldcg(&g_slot[e])] = c;
        }
    }

    // ---- phase 4: GEMM, persistent tiles, dinv folded into epilogue ----
    {
        float*    sA[2] = {dyn, dyn + A_BUF};
        uint32_t* sWb   = reinterpret_cast<uint32_t*>(dyn + 2 * A_BUF);
        uint32_t* sW[2] = {sWb, sWb + W_BUF};

        int warp = tid >> 5;
        int lane = tid & 31;
        int gid  = lane >> 2;
        int tig  = lane & 3;
        int mw   = warp * 16;

        auto loadA = [&](int m0, int k0, float* buf) {
#pragma unroll
            for (int it = 0; it < 4; it++) {
                int idx = tid + it * 256;
                int m   = idx >> 3;
                int kq  = idx & 7;
                int gm  = m0 + m;
                int ok  = gm < N;
                int row = ok ? gm : 0;
                cp16(&buf[m * AS + kq * 4], &x[(size_t)row * IN_SIZE + k0 + kq * 4], ok);
            }
        };
        auto loadW = [&](int k0, uint32_t* buf) {
#pragma unroll
            for (int it = 0; it < 2; it++) {
                int idx = tid + it * 256;
                int k   = idx >> 4;
                int nq  = idx & 15;
                cp16(&buf[k * WS + nq * 4], &g_wt[(k0 + k) * OUT_SIZE + nq * 4], 1);
            }
        };

        for (int t = blockIdx.x; t < tiles; t += nBlocks) {
            int m0 = t * GM;

            float acc[8][4];
#pragma unroll
            for (int j = 0; j < 8; j++)
#pragma unroll
                for (int q = 0; q < 4; q++) acc[j][q] = 0.0f;

            __syncthreads();   // smem reuse guard (scan scratch / previous tile)
            loadA(m0, 0, sA[0]);
            loadW(0, sW[0]);
            cp_commit();

#pragma unroll 1
            for (int i = 0; i < IN_SIZE / GK; i++) {
                if (i < IN_SIZE / GK - 1) {
                    loadA(m0, (i + 1) * GK, sA[(i + 1) & 1]);
                    loadW((i + 1) * GK, sW[(i + 1) & 1]);
                    cp_commit();
                    cp_wait<1>();
                } else {
                    cp_wait<0>();
                }
                __syncthreads();

                const float*    a_s = sA[i & 1];
                const uint32_t* w_s = sW[i & 1];
#pragma unroll
                for (int ks = 0; ks < 4; ks++) {
                    int kk = ks * 8;
                    uint32_t a0 = f2tf(a_s[(mw + gid)     * AS + kk + tig]);
                    uint32_t a1 = f2tf(a_s[(mw + gid + 8) * AS + kk + tig]);
                    uint32_t a2 = f2tf(a_s[(mw + gid)     * AS + kk + tig + 4]);
                    uint32_t a3 = f2tf(a_s[(mw + gid + 8) * AS + kk + tig + 4]);
#pragma unroll
                    for (int j = 0; j < 8; j++) {
                        uint32_t b0 = w_s[(kk + tig)     * WS + j * 8 + gid];
                        uint32_t b1 = w_s[(kk + tig + 4) * WS + j * 8 + gid];
                        asm volatile(
                            "mma.sync.aligned.m16n8k8.row.col.f32.tf32.tf32.f32 "
                            "{%0,%1,%2,%3}, {%4,%5,%6,%7}, {%8,%9}, {%0,%1,%2,%3};"
                            : "+f"(acc[j][0]), "+f"(acc[j][1]), "+f"(acc[j][2]), "+f"(acc[j][3])
                            : "r"(a0), "r"(a1), "r"(a2), "r"(a3), "r"(b0), "r"(b1));
                    }
                }
                __syncthreads();
            }

            // epilogue: scale by dinv (ready since phase 2), write fp16
            int r0 = m0 + mw + gid;
            float d0 = (r0 < N)     ? g_dinv[r0]     : 0.0f;
            float d1 = (r0 + 8 < N) ? g_dinv[r0 + 8] : 0.0f;
#pragma unroll
            for (int j = 0; j < 8; j++) {
                if (r0 < N) {
                    __half2 h = __floats2half2_rn(d0 * acc[j][0], d0 * acc[j][1]);
                    *reinterpret_cast<__half2*>(&g_xwh[(size_t)r0 * OUT_SIZE + j * 8 + 2 * tig]) = h;
                }
                if (r0 + 8 < N) {
                    __half2 h = __floats2half2_rn(d1 * acc[j][2], d1 * acc[j][3]);
                    *reinterpret_cast<__half2*>(&g_xwh[(size_t)(r0 + 8) * OUT_SIZE + j * 8 + 2 * tig]) = h;
                }
            }
        }
    }
}

// ---------------- aggregation: out[r] = dinv[r]*(xwh[r] + sum_c xwh[c]) ----------------
__device__ __forceinline__ void h8_add(uint4 v, float* acc) {
    const __half2* h = reinterpret_cast<const __half2*>(&v);
#pragma unroll
    for (int q = 0; q < 4; q++) {
        float2 f = __half22float2(h[q]);
        acc[2 * q]     += f.x;
        acc[2 * q + 1] += f.y;
    }
}

__device__ __forceinline__ uint4 h8_pair(uint4 a, uint4 b) {
    const __half2* ha = reinterpret_cast<const __half2*>(&a);
    const __half2* hb = reinterpret_cast<const __half2*>(&b);
    uint4 r;
    __half2* hr = reinterpret_cast<__half2*>(&r);
#pragma unroll
    for (int q = 0; q < 4; q++) hr[q] = __hadd2(ha[q], hb[q]);
    return r;
}

__global__ __launch_bounds__(256) void k_agg(float* __restrict__ out, int N) {
    // reset mega's counters for the next replay (no agg block reads them)
    if (blockIdx.x == 0 && threadIdx.x == 0) {
        g_gctr = 0u; g_total = 0;
    }

    int t   = blockIdx.x * blockDim.x + threadIdx.x;
    int row = t >> 3;          // 8 lanes per row
    int l   = t & 7;
    if (row >= N) return;

    const uint4* xh = reinterpret_cast<const uint4*>(g_xwh);
    float dr = g_dinv[row];
    unsigned gmask = 0xffu << (((threadIdx.x & 31) >> 3) << 3);   // my 8-lane subgroup

    float acc[8];
#pragma unroll
    for (int q = 0; q < 8; q++) acc[q] = 0.0f;
    h8_add(xh[(size_t)row * 8 + l], acc);   // self loop (already dinv-scaled)

    int s0  = g_rowstart[row];
    int cnt = g_deg[row];

    int j = 0;
    // 8-edge chunks: one coalesced col load per lane, shfl-broadcast within group
    for (; j + 8 <= cnt; j += 8) {
        int ci = __ldg(&g_col[s0 + j + l]);
#pragma unroll
        for (int k = 0; k < 8; k += 2) {
            int ca = __shfl_sync(gmask, ci, k,     8);
            int cb = __shfl_sync(gmask, ci, k + 1, 8);
            uint4 va = xh[(size_t)ca * 8 + l];
            uint4 vb = xh[(size_t)cb * 8 + l];
            h8_add(h8_pair(va, vb), acc);
        }
    }
    for (; j < cnt; j++) {
        int c = __ldg(&g_col[s0 + j]);
        h8_add(xh[(size_t)c * 8 + l], acc);
    }

    float4 o0 = make_float4(dr * acc[0], dr * acc[1], dr * acc[2], dr * acc[3]);
    float4 o1 = make_float4(dr * acc[4], dr * acc[5], dr * acc[6], dr * acc[7]);
    float4* dst = reinterpret_cast<float4*>(out + (size_t)row * OUT_SIZE + l * 8);
    dst[0] = o0;
    dst[1] = o1;
}

// ---------------------------------------------------------------------------
extern "C" void kernel_launch(void* const* d_in, const int* in_sizes, int n_in,
                              void* d_out, int out_size) {
    const int*   ei = (const int*)d_in[0];     // [2, E]
    const float* x  = (const float*)d_in[1];   // [N, 256]
    const float* W  = (const float*)d_in[3];   // [64, 256]
    float* out = (float*)d_out;

    int E = in_sizes[0] / 2;
    int N = in_sizes[1] / IN_SIZE;

    cudaFuncSetAttribute(k_mega, cudaFuncAttributeMaxDynamicSharedMemorySize, GEMM_SMEM);

    int dev = 0;
    cudaGetDevice(&dev);
    int sms = 0;
    cudaDeviceGetAttribute(&sms, cudaDevAttrMultiProcessorCount, dev);
    int mb = 0;
    cudaOccupancyMaxActiveBlocksPerMultiprocessor(&mb, k_mega, 256, GEMM_SMEM);
    if (mb < 1) mb = 1;
    if (sms < 1) sms = 148;

    int nBlocks = sms * mb;                       // exactly one resident wave
    int tiles   = (N + GM - 1) / GM;

    k_mega<<<nBlocks, 256, GEMM_SMEM>>>(ei, x, W, N, E, tiles, nBlocks);
    k_agg <<<(N * 8 + 255) / 256, 256>>>(out, N);
}

// round 17
// speedup vs baseline: 1.1268x; 1.0746x over previous
#include <cuda_runtime.h>
#include <cuda_fp16.h>
#include <math.h>
#include <stdint.h>

#define MAXN 100000
#define MAXE 1600000
#define IN_SIZE 256
#define OUT_SIZE 64
#define CAP 64                  // bucket capacity per row (Poisson(16) -> max ~45)
#define MAXOVF 4096

// ---------------- device scratch (no allocation allowed) ----------------
__device__ __align__(256) __half    g_xwh[MAXN * OUT_SIZE];     // dinv-scaled X@W^T fp16
__device__ __align__(256) uint32_t  g_wt[IN_SIZE * OUT_SIZE];   // W^T tf32, [k][n]
__device__ __align__(256) float     g_dinv[MAXN];               // D^{-1/2}
__device__ __align__(256) int       g_deg[MAXN];                // non-self degree
__device__ __align__(256) int       g_col2[MAXN * CAP];         // bucketed CSR columns
__device__ __align__(256) int       g_ovf[MAXOVF * 2];          // overflow (r,c) pairs
__device__ int      g_ovf_n;      // overflow count (reset by k_ovf)
__device__ unsigned g_gctr;       // grid barrier counter (reset by k_ovf)

__device__ __forceinline__ uint32_t f2tf(float f) {
    uint32_t r;
    asm("cvt.rna.tf32.f32 %0, %1;" : "=r"(r) : "f"(f));
    return r;
}

__device__ __forceinline__ void cp16(void* smem, const void* g, int valid) {
    uint32_t s = (uint32_t)__cvta_generic_to_shared(smem);
    asm volatile("cp.async.cg.shared.global [%0], [%1], 16, %2;"
                 :: "r"(s), "l"(g), "r"(valid ? 16 : 0));
}
__device__ __forceinline__ void cp_commit() { asm volatile("cp.async.commit_group;"); }
template <int n> __device__ __forceinline__ void cp_wait() {
    asm volatile("cp.async.wait_group %0;" :: "n"(n));
}

__device__ __forceinline__ unsigned ld_acq(const unsigned* p) {
    unsigned v;
    asm volatile("ld.acquire.gpu.u32 %0, [%1];" : "=r"(v) : "l"(p) : "memory");
    return v;
}

// full-grid barrier (one-wave grid), monotonic counter
__device__ __forceinline__ void grid_barrier(int phase, int nBlocks) {
    __syncthreads();
    if (threadIdx.x == 0) {
        __threadfence();
        atomicAdd(&g_gctr, 1u);
        unsigned target = (unsigned)(phase * nBlocks);
        while (ld_acq(&g_gctr) < target) __nanosleep(64);
    }
    __syncthreads();
}

// ---------------- mega: zero+Wconv | fill | dinv | GEMM (serial, full chip) ----------------
#define GM 128
#define GK 32
#define AS 36
#define WS 72
#define A_BUF (GM * AS)
#define W_BUF (GK * WS)
#define GEMM_SMEM ((2 * A_BUF + 2 * W_BUF) * 4)   // 55296 B

__global__ __launch_bounds__(256) void k_mega(const int* __restrict__ ei,
                                              const float* __restrict__ x,
                                              const float* __restrict__ W,
                                              int N, int E, int tiles, int nBlocks) {
    extern __shared__ float dyn[];
    int tid  = threadIdx.x;
    int gtid = blockIdx.x * 256 + tid;
    int T    = nBlocks * 256;

    // ---- phase 0: zero degrees + W^T tf32 convert ----
    for (int i = gtid; i < N; i += T) g_deg[i] = 0;
    for (int i = gtid; i < IN_SIZE * OUT_SIZE; i += T) {
        int k = i >> 6;
        int n = i & 63;
        g_wt[i] = f2tf(W[n * IN_SIZE + k]);
    }
    grid_barrier(1, nBlocks);

    // ---- phase 1: single-pass bucket fill (count + place fused) ----
    {
        int e = gtid;
        for (; e + 3 * T < E; e += 4 * T) {
            int e0 = e, e1 = e + T, e2 = e + 2 * T, e3 = e + 3 * T;
            int r0 = ei[e0], r1 = ei[e1], r2 = ei[e2], r3 = ei[e3];
            int c0 = ei[E + e0], c1 = ei[E + e1], c2 = ei[E + e2], c3 = ei[E + e3];
#define FILL_ONE(rr, cc)                                                     \
            if ((rr) != (cc)) {                                              \
                int sl = atomicAdd(&g_deg[rr], 1);                           \
                if (sl < CAP) g_col2[((rr) << 6) + sl] = (cc);               \
                else {                                                       \
                    int o = atomicAdd(&g_ovf_n, 1);                          \
                    if (o < MAXOVF) { g_ovf[2 * o] = (rr); g_ovf[2 * o + 1] = (cc); } \
                }                                                            \
            }
            FILL_ONE(r0, c0)
            FILL_ONE(r1, c1)
            FILL_ONE(r2, c2)
            FILL_ONE(r3, c3)
        }
        for (; e < E; e += T) {
            int r = ei[e], c = ei[E + e];
            FILL_ONE(r, c)
        }
#undef FILL_ONE
    }
    grid_barrier(2, nBlocks);

    // ---- phase 2: dinv = (deg+1)^{-1/2} ----
    for (int i = gtid; i < N; i += T)
        g_dinv[i] = rsqrtf((float)(__ldcg(&g_deg[i]) + 1));
    grid_barrier(3, nBlocks);

    // ---- phase 3: GEMM, persistent tiles, dinv folded into epilogue ----
    {
        float*    sA[2] = {dyn, dyn + A_BUF};
        uint32_t* sWb   = reinterpret_cast<uint32_t*>(dyn + 2 * A_BUF);
        uint32_t* sW[2] = {sWb, sWb + W_BUF};

        int warp = tid >> 5;
        int lane = tid & 31;
        int gid  = lane >> 2;
        int tig  = lane & 3;
        int mw   = warp * 16;

        auto loadA = [&](int m0, int k0, float* buf) {
#pragma unroll
            for (int it = 0; it < 4; it++) {
                int idx = tid + it * 256;
                int m   = idx >> 3;
                int kq  = idx & 7;
                int gm  = m0 + m;
                int ok  = gm < N;
                int row = ok ? gm : 0;
                cp16(&buf[m * AS + kq * 4], &x[(size_t)row * IN_SIZE + k0 + kq * 4], ok);
            }
        };
        auto loadW = [&](int k0, uint32_t* buf) {
#pragma unroll
            for (int it = 0; it < 2; it++) {
                int idx = tid + it * 256;
                int k   = idx >> 4;
                int nq  = idx & 15;
                cp16(&buf[k * WS + nq * 4], &g_wt[(k0 + k) * OUT_SIZE + nq * 4], 1);
            }
        };

        for (int t = blockIdx.x; t < tiles; t += nBlocks) {
            int m0 = t * GM;

            float acc[8][4];
#pragma unroll
            for (int j = 0; j < 8; j++)
#pragma unroll
                for (int q = 0; q < 4; q++) acc[j][q] = 0.0f;

            __syncthreads();   // smem reuse guard between tiles
            loadA(m0, 0, sA[0]);
            loadW(0, sW[0]);
            cp_commit();

#pragma unroll 1
            for (int i = 0; i < IN_SIZE / GK; i++) {
                if (i < IN_SIZE / GK - 1) {
                    loadA(m0, (i + 1) * GK, sA[(i + 1) & 1]);
                    loadW((i + 1) * GK, sW[(i + 1) & 1]);
                    cp_commit();
                    cp_wait<1>();
                } else {
                    cp_wait<0>();
                }
                __syncthreads();

                const float*    a_s = sA[i & 1];
                const uint32_t* w_s = sW[i & 1];
#pragma unroll
                for (int ks = 0; ks < 4; ks++) {
                    int kk = ks * 8;
                    uint32_t a0 = f2tf(a_s[(mw + gid)     * AS + kk + tig]);
                    uint32_t a1 = f2tf(a_s[(mw + gid + 8) * AS + kk + tig]);
                    uint32_t a2 = f2tf(a_s[(mw + gid)     * AS + kk + tig + 4]);
                    uint32_t a3 = f2tf(a_s[(mw + gid + 8) * AS + kk + tig + 4]);
#pragma unroll
                    for (int j = 0; j < 8; j++) {
                        uint32_t b0 = w_s[(kk + tig)     * WS + j * 8 + gid];
                        uint32_t b1 = w_s[(kk + tig + 4) * WS + j * 8 + gid];
                        asm volatile(
                            "mma.sync.aligned.m16n8k8.row.col.f32.tf32.tf32.f32 "
                            "{%0,%1,%2,%3}, {%4,%5,%6,%7}, {%8,%9}, {%0,%1,%2,%3};"
                            : "+f"(acc[j][0]), "+f"(acc[j][1]), "+f"(acc[j][2]), "+f"(acc[j][3])
                            : "r"(a0), "r"(a1), "r"(a2), "r"(a3), "r"(b0), "r"(b1));
                    }
                }
                __syncthreads();
            }

            // epilogue: scale by dinv, write fp16
            int r0 = m0 + mw + gid;
            float d0 = (r0 < N)     ? g_dinv[r0]     : 0.0f;
            float d1 = (r0 + 8 < N) ? g_dinv[r0 + 8] : 0.0f;
#pragma unroll
            for (int j = 0; j < 8; j++) {
                if (r0 < N) {
                    __half2 h = __floats2half2_rn(d0 * acc[j][0], d0 * acc[j][1]);
                    *reinterpret_cast<__half2*>(&g_xwh[(size_t)r0 * OUT_SIZE + j * 8 + 2 * tig]) = h;
                }
                if (r0 + 8 < N) {
                    __half2 h = __floats2half2_rn(d1 * acc[j][2], d1 * acc[j][3]);
                    *reinterpret_cast<__half2*>(&g_xwh[(size_t)(r0 + 8) * OUT_SIZE + j * 8 + 2 * tig]) = h;
                }
            }
        }
    }
}

// ---------------- aggregation: out[r] = dinv[r]*(xwh[r] + sum_c xwh[c]) ----------------
__device__ __forceinline__ void h8_add(uint4 v, float* acc) {
    const __half2* h = reinterpret_cast<const __half2*>(&v);
#pragma unroll
    for (int q = 0; q < 4; q++) {
        float2 f = __half22float2(h[q]);
        acc[2 * q]     += f.x;
        acc[2 * q + 1] += f.y;
    }
}

__device__ __forceinline__ uint4 h8_pair(uint4 a, uint4 b) {
    const __half2* ha = reinterpret_cast<const __half2*>(&a);
    const __half2* hb = reinterpret_cast<const __half2*>(&b);
    uint4 r;
    __half2* hr = reinterpret_cast<__half2*>(&r);
#pragma unroll
    for (int q = 0; q < 4; q++) hr[q] = __hadd2(ha[q], hb[q]);
    return r;
}

__global__ __launch_bounds__(256) void k_agg(float* __restrict__ out, int N) {
    int t   = blockIdx.x * blockDim.x + threadIdx.x;
    int row = t >> 3;          // 8 lanes per row
    int l   = t & 7;
    if (row >= N) return;

    const uint4* xh = reinterpret_cast<const uint4*>(g_xwh);
    float dr = g_dinv[row];

    float acc[8];
#pragma unroll
    for (int q = 0; q < 8; q++) acc[q] = 0.0f;
    h8_add(xh[(size_t)row * 8 + l], acc);   // self loop (already dinv-scaled)

    int s0  = row << 6;                      // bucket base
    int cnt = g_deg[row];
    if (cnt > CAP) cnt = CAP;                // overflow handled by k_ovf

    int j = 0;
    for (; j + 4 <= cnt; j += 4) {
        int c0 = __ldg(&g_col2[s0 + j]);
        int c1 = __ldg(&g_col2[s0 + j + 1]);
        int c2 = __ldg(&g_col2[s0 + j + 2]);
        int c3 = __ldg(&g_col2[s0 + j + 3]);
        uint4 v0 = xh[(size_t)c0 * 8 + l];
        uint4 v1 = xh[(size_t)c1 * 8 + l];
        uint4 v2 = xh[(size_t)c2 * 8 + l];
        uint4 v3 = xh[(size_t)c3 * 8 + l];
        h8_add(h8_pair(v0, v1), acc);
        h8_add(h8_pair(v2, v3), acc);
    }
    for (; j < cnt; j++) {
        int c = __ldg(&g_col2[s0 + j]);
        h8_add(xh[(size_t)c * 8 + l], acc);
    }

    float4 o0 = make_float4(dr * acc[0], dr * acc[1], dr * acc[2], dr * acc[3]);
    float4 o1 = make_float4(dr * acc[4], dr * acc[5], dr * acc[6], dr * acc[7]);
    float4* dst = reinterpret_cast<float4*>(out + (size_t)row * OUT_SIZE + l * 8);
    dst[0] = o0;
    dst[1] = o1;
}

// ---------------- overflow fixup (normally 0 edges) + counter reset ----------------
__global__ void k_ovf(float* __restrict__ out, int N) {
    int n = g_ovf_n;
    if (n > MAXOVF) n = MAXOVF;
    // single block: 16 lanes per overflow edge, red.global adds
    for (int idx = threadIdx.x; idx < n * 16; idx += 256) {
        int e = idx >> 4;
        int l = idx & 15;
        int r = g_ovf[2 * e];
        int c = g_ovf[2 * e + 1];
        float dr = g_dinv[r];
        const uint2* xh2 = reinterpret_cast<const uint2*>(g_xwh);
        uint2 v = xh2[(size_t)c * 16 + l];           // 4 halves
        const __half2* h = reinterpret_cast<const __half2*>(&v);
        float2 f0 = __half22float2(h[0]);
        float2 f1 = __half22float2(h[1]);
        float* dst = out + (size_t)r * OUT_SIZE + l * 4;
        asm volatile("red.global.add.v4.f32 [%0], {%1, %2, %3, %4};"
                     :: "l"(dst), "f"(dr * f0.x), "f"(dr * f0.y),
                        "f"(dr * f1.x), "f"(dr * f1.y) : "memory");
    }
    __syncthreads();
    if (threadIdx.x == 0) { g_gctr = 0u; g_ovf_n = 0; }   // reset for next replay
}

// ---------------------------------------------------------------------------
extern "C" void kernel_launch(void* const* d_in, const int* in_sizes, int n_in,
                              void* d_out, int out_size) {
    const int*   ei = (const int*)d_in[0];     // [2, E]
    const float* x  = (const float*)d_in[1];   // [N, 256]
    const float* W  = (const float*)d_in[3];   // [64, 256]
    float* out = (float*)d_out;

    int E = in_sizes[0] / 2;
    int N = in_sizes[1] / IN_SIZE;

    cudaFuncSetAttribute(k_mega, cudaFuncAttributeMaxDynamicSharedMemorySize, GEMM_SMEM);

    int dev = 0;
    cudaGetDevice(&dev);
    int sms = 0;
    cudaDeviceGetAttribute(&sms, cudaDevAttrMultiProcessorCount, dev);
    int mb = 0;
    cudaOccupancyMaxActiveBlocksPerMultiprocessor(&mb, k_mega, 256, GEMM_SMEM);
    if (mb < 1) mb = 1;
    if (sms < 1) sms = 148;

    int nBlocks = sms * mb;                       // exactly one resident wave
    int tiles   = (N + GM - 1) / GM;

    k_mega<<<nBlocks, 256, GEMM_SMEM>>>(ei, x, W, N, E, tiles, nBlocks);
    k_agg <<<(N * 8 + 255) / 256, 256>>>(out, N);
    k_ovf <<<1, 256>>>(out, N);
}